// round 10
// baseline (speedup 1.0000x reference)
#include <cuda_runtime.h>
#include <cuda_fp16.h>
#include <math.h>

// BilateralSlice: out[b,c,i,j] = trilinear(grid[b,c, h(j), w(i), d(guide[b,i,j])])
// Shapes: grid (4,12,16,16,8) f32, guide (4,1,1024,1024) f32, out (4,12,1024,1024) f32.
//
// R10: four CTAs per image row (256 cols, 1 col/thread) to cut registers to
// <=42 and reach 6 CTAs/SM (75% occupancy; R9 was capped at 50% and was
// latency-bound with no saturated pipe). fp16 w-lerped slab as before:
// quarter-row touches <=6 h-slices -> 6*112 halves = 1.3 KB smem, staged in
// one pass. Per pixel: 4 corners x 24 B = 96 B LDS, fp32 accumulate.

#define CC   12
#define HG   16
#define DG   8
#define HH   1024
#define WW_  1024

#define DSTRIDE_H 12          // halves per d
#define HSTRIDE_H 112         // halves per h (96 + 16 pad)
#define DSTRIDE_B 24          // bytes
#define HSTRIDE_B 224         // bytes
#define NSLICE    6           // h-slices per quarter-row (max)

__device__ __forceinline__ void corner_acc(const char* sb, int off, float w, float* acc)
{
    uint2 p0 = *(const uint2*)(sb + off);        // halves c0..c3
    uint2 p1 = *(const uint2*)(sb + off + 8);    // c4..c7
    uint2 p2 = *(const uint2*)(sb + off + 16);   // c8..c11
    float2 f;
    f = __half22float2(*(const __half2*)&p0.x); acc[0] = fmaf(w, f.x, acc[0]); acc[1] = fmaf(w, f.y, acc[1]);
    f = __half22float2(*(const __half2*)&p0.y); acc[2] = fmaf(w, f.x, acc[2]); acc[3] = fmaf(w, f.y, acc[3]);
    f = __half22float2(*(const __half2*)&p1.x); acc[4] = fmaf(w, f.x, acc[4]); acc[5] = fmaf(w, f.y, acc[5]);
    f = __half22float2(*(const __half2*)&p1.y); acc[6] = fmaf(w, f.x, acc[6]); acc[7] = fmaf(w, f.y, acc[7]);
    f = __half22float2(*(const __half2*)&p2.x); acc[8] = fmaf(w, f.x, acc[8]); acc[9] = fmaf(w, f.y, acc[9]);
    f = __half22float2(*(const __half2*)&p2.y); acc[10] = fmaf(w, f.x, acc[10]); acc[11] = fmaf(w, f.y, acc[11]);
}

__global__ void __launch_bounds__(256, 6)
bslice_kernel(const float* __restrict__ grid,
              const float* __restrict__ guide,
              float* __restrict__ out)
{
    __shared__ __half sh[NSLICE * HSTRIDE_H];   // 672 halves = 1344 B
    const char* sb = (const char*)sh;

    const int q = blockIdx.x & 3;           // quarter within row
    const int i = blockIdx.x >> 2;          // image row
    const int b = blockIdx.y;
    const int t = threadIdx.x;
    const int j0 = q * 256;
    const int hbase = (j0 * 15) / 1023;     // first h-slice this quarter touches

    // ---- w cell for this row (constant across the row) ----
    const float wwf = (float)i * (15.0f / 1023.0f);
    int w0 = (int)wwf; if (w0 > 15) w0 = 15;
    int w1 = w0 + 1;   if (w1 > 15) w1 = 15;
    const float fw = wwf - (float)w0;

    // ---- Stage w-interpolated slab (fp32 lerp, fp16 store): 144 groups ----
    const float4* g4 = (const float4*)grid;
    if (t < 144) {                          // 12c * 6h * 2 d-quads
        int c   = t / 12;
        int rem = t - c * 12;
        int h   = rem >> 1;
        int dq  = rem & 1;
        int hg  = hbase + h; if (hg > 15) hg = 15;   // clamp (top quarter has 5 slices)
        int base = ((b * CC + c) * HG + hg) * 32;    // float4 off of [b,c,hg,0,0]
        float4 a  = g4[base + w0 * 2 + dq];
        float4 bb = g4[base + w1 * 2 + dq];
        int so = h * HSTRIDE_H + (dq * 4) * DSTRIDE_H + c;
        sh[so]                 = __float2half_rn(fmaf(fw, bb.x - a.x, a.x));
        sh[so + DSTRIDE_H]     = __float2half_rn(fmaf(fw, bb.y - a.y, a.y));
        sh[so + 2 * DSTRIDE_H] = __float2half_rn(fmaf(fw, bb.z - a.z, a.z));
        sh[so + 3 * DSTRIDE_H] = __float2half_rn(fmaf(fw, bb.w - a.w, a.w));
    }
    __syncthreads();

    // ---- One pixel per thread ----
    const int j = j0 + t;

    float hhf = (float)j * (15.0f / 1023.0f);
    int h0 = (int)hhf; if (h0 > 15) h0 = 15;
    int h1 = h0 + 1;   if (h1 > 15) h1 = 15;
    const float fh = hhf - (float)h0;
    const int ho0 = (h0 - hbase) * HSTRIDE_B;
    const int ho1 = (h1 - hbase) * HSTRIDE_B;

    const float g = guide[((size_t)b * HH + i) * WW_ + j];
    float dc  = g * 7.0f;
    float dfl = floorf(dc);
    dfl = fminf(fmaxf(dfl, 0.0f), 7.0f);
    int d0 = (int)dfl;
    int d1 = d0 + 1; if (d1 > 7) d1 = 7;
    float dw = fminf(fmaxf(dc - dfl, 0.0f), 1.0f);

    const float w00 = (1.0f - fh) * (1.0f - dw);
    const float w01 = (1.0f - fh) * dw;
    const float w10 = fh * (1.0f - dw);
    const float w11 = fh * dw;

    float acc[12];
    #pragma unroll
    for (int c = 0; c < 12; c++) acc[c] = 0.0f;

    corner_acc(sb, ho0 + d0 * DSTRIDE_B, w00, acc);
    corner_acc(sb, ho0 + d1 * DSTRIDE_B, w01, acc);
    corner_acc(sb, ho1 + d0 * DSTRIDE_B, w10, acc);
    corner_acc(sb, ho1 + d1 * DSTRIDE_B, w11, acc);

    // ---- Coalesced scalar stores: 12 channels ----
    float* op = out + (((size_t)b * CC) * HH + i) * WW_ + j;
    #pragma unroll
    for (int c = 0; c < 12; c++)
        op[(size_t)c * (HH * WW_)] = acc[c];
}

extern "C" void kernel_launch(void* const* d_in, const int* in_sizes, int n_in,
                              void* d_out, int out_size)
{
    const float* grid  = (const float*)d_in[0];
    const float* guide = (const float*)d_in[1];
    float* out = (float*)d_out;

    dim3 gr(HH * 4, 4);                     // four CTAs per (row, batch)
    bslice_kernel<<<gr, 256>>>(grid, guide, out);
}